// round 13
// baseline (speedup 1.0000x reference)
#include <cuda_runtime.h>
#include <math.h>

#define T_STEPS 1000
#define BATCH   16
#define MEL     80
#define HID     512
#define NCLS    64
#define NROWS   (T_STEPS*BATCH)      // 16000

#define NGROUPS   8
#define GCTAS     16                 // CTAs per group (sync domain)
#define SCAN_CTAS (NGROUPS*GCTAS)    // 128
#define GCOLS     32                 // cols per CTA
#define WSL       20                 // padded k-slice stride (16 data + 4 pad floats)

// ---------------- scratch (device globals; no allocation allowed) ----------
__device__ float    g_be0[NROWS*HID];
__device__ float    g_xn1[NROWS*HID];
__device__ float    g_be1[NROWS*HID];
__device__ float    g_hall[NROWS*HID];
__device__ float    g_scale1[NROWS];
__device__ float    g_err[BATCH*HID];
__device__ float    g_normp[BATCH*128];   // [b][cta_in_group*8 + warp]
__device__ float    g_hzero[BATCH*HID];
__device__ __align__(64) unsigned g_flagA[NGROUPS*16];  // per-CTA phase flags

__device__ __forceinline__ float clip1(float v) {
    return fminf(fmaxf(v, -1.f), 1.f);
}

// ---------------- fused: zero scratch + xnorm0 + be0 GEMM ------------------
__global__ __launch_bounds__(256) void fused_be0_kernel(
    const float* __restrict__ feats, const float* __restrict__ B0)
{
    __shared__ float xs[64][80];

    const int tid  = threadIdx.x;
    const int warp = tid >> 5, lane = tid & 31;
    const int r_base = blockIdx.x*64 + warp*8;

    if (blockIdx.x == 0) {
        if (tid < NGROUPS*16) g_flagA[tid] = 0u;
        for (int i = tid; i < BATCH*HID; i += 256) g_hzero[i] = 0.f;
    }

    #pragma unroll
    for (int rr = 0; rr < 8; rr++) {
        int r = r_base + rr;
        int t = r >> 4, b = r & 15;
        const float* row = feats + ((size_t)b*T_STEPS + t)*MEL;
        float v0 = row[lane];
        float v1 = row[lane+32];
        float v2 = (lane < 16) ? row[lane+64] : 0.f;
        float s = v0*v0 + v1*v1 + v2*v2;
        #pragma unroll
        for (int off = 16; off; off >>= 1) s += __shfl_xor_sync(0xffffffffu, s, off);
        float inv = 1.f/fmaxf(sqrtf(s), 1e-6f);
        int lr = warp*8 + rr;
        xs[lr][lane]    = clip1(v0*inv);
        xs[lr][lane+32] = clip1(v1*inv);
        if (lane < 16) xs[lr][lane+64] = clip1(v2*inv);
    }
    __syncwarp();

    #pragma unroll 1
    for (int q = 0; q < 4; q++) {
        int c0 = q*128 + lane*4;
        float acc[8][4];
        #pragma unroll
        for (int rr = 0; rr < 8; rr++)
            #pragma unroll
            for (int j = 0; j < 4; j++) acc[rr][j] = 0.f;

        for (int kc = 0; kc < 20; kc++) {
            float4 b40 = *(const float4*)(B0 + (size_t)(c0+0)*MEL + kc*4);
            float4 b41 = *(const float4*)(B0 + (size_t)(c0+1)*MEL + kc*4);
            float4 b42 = *(const float4*)(B0 + (size_t)(c0+2)*MEL + kc*4);
            float4 b43 = *(const float4*)(B0 + (size_t)(c0+3)*MEL + kc*4);
            #pragma unroll
            for (int rr = 0; rr < 8; rr++) {
                float4 x4 = *(const float4*)&xs[warp*8+rr][kc*4];
                acc[rr][0] += x4.x*b40.x + x4.y*b40.y + x4.z*b40.z + x4.w*b40.w;
                acc[rr][1] += x4.x*b41.x + x4.y*b41.y + x4.z*b41.z + x4.w*b41.w;
                acc[rr][2] += x4.x*b42.x + x4.y*b42.y + x4.z*b42.z + x4.w*b42.w;
                acc[rr][3] += x4.x*b43.x + x4.y*b43.y + x4.z*b43.z + x4.w*b43.w;
            }
        }
        #pragma unroll
        for (int rr = 0; rr < 8; rr++) {
            int r = r_base + rr;
            *(float4*)&g_be0[(size_t)r*HID + c0] =
                make_float4(acc[rr][0], acc[rr][1], acc[rr][2], acc[rr][3]);
        }
    }
}

// ---------------- x_norm + scale for cell1 input (be0) ---------------------
__global__ void xnorm1_kernel() {
    int w    = (blockIdx.x*blockDim.x + threadIdx.x) >> 5;
    int lane = threadIdx.x & 31;
    if (w >= NROWS) return;
    const float4* row = (const float4*)(g_be0 + (size_t)w*HID);
    float4 v[4];
    float s = 0.f;
    #pragma unroll
    for (int i = 0; i < 4; i++) {
        v[i] = row[lane + 32*i];
        s += v[i].x*v[i].x + v[i].y*v[i].y + v[i].z*v[i].z + v[i].w*v[i].w;
    }
    #pragma unroll
    for (int off = 16; off; off >>= 1) s += __shfl_xor_sync(0xffffffffu, s, off);
    float sc = fmaxf(sqrtf(s), 1e-6f);
    if (lane == 0) g_scale1[w] = sc;
    float inv = 1.f/sc;
    float4* o = (float4*)(g_xn1 + (size_t)w*HID);
    #pragma unroll
    for (int i = 0; i < 4; i++) {
        float4 u = v[i];
        u.x = clip1(u.x*inv);
        u.y = clip1(u.y*inv);
        u.z = clip1(u.z*inv);
        u.w = clip1(u.w*inv);
        o[lane + 32*i] = u;
    }
}

// ---------------- generic tiled SGEMM: C = A(M,K) @ W(N,K)^T ---------------
__global__ __launch_bounds__(256) void sgemm_nt(
    const float* __restrict__ A, int lda,
    const float* __restrict__ W, int ldw,
    float*       __restrict__ C, int ldc,
    int K, int accumulate, const float* __restrict__ bias, int remap)
{
    __shared__ float As[16][64];
    __shared__ float Ws[16][64];
    int bm = blockIdx.y*64, bn = blockIdx.x*64;
    int tid = threadIdx.x;
    int lr  = tid >> 2;
    int kq  = (tid & 3)*4;
    int tx  = tid & 15, ty = tid >> 4;
    float acc[4][4];
    #pragma unroll
    for (int i=0;i<4;i++)
        #pragma unroll
        for (int j=0;j<4;j++) acc[i][j]=0.f;

    for (int k0 = 0; k0 < K; k0 += 16) {
        float4 av = *(const float4*)(A + (size_t)(bm+lr)*lda + k0 + kq);
        float4 wv = *(const float4*)(W + (size_t)(bn+lr)*ldw + k0 + kq);
        As[kq+0][lr]=av.x; As[kq+1][lr]=av.y; As[kq+2][lr]=av.z; As[kq+3][lr]=av.w;
        Ws[kq+0][lr]=wv.x; Ws[kq+1][lr]=wv.y; Ws[kq+2][lr]=wv.z; Ws[kq+3][lr]=wv.w;
        __syncthreads();
        #pragma unroll
        for (int k = 0; k < 16; k++) {
            float4 a4 = *(float4*)&As[k][ty*4];
            float4 w4 = *(float4*)&Ws[k][tx*4];
            float ar[4] = {a4.x, a4.y, a4.z, a4.w};
            float wr[4] = {w4.x, w4.y, w4.z, w4.w};
            #pragma unroll
            for (int i=0;i<4;i++)
                #pragma unroll
                for (int j=0;j<4;j++) acc[i][j] += ar[i]*wr[j];
        }
        __syncthreads();
    }
    #pragma unroll
    for (int i = 0; i < 4; i++) {
        int r = bm + ty*4 + i;
        int orow = remap ? ((r & 15)*T_STEPS + (r >> 4)) : r;
        #pragma unroll
        for (int j = 0; j < 4; j++) {
            int cidx = bn + tx*4 + j;
            float val = acc[i][j];
            if (bias) val += bias[cidx];
            float* p = C + (size_t)orow*ldc + cidx;
            if (accumulate) val += *p;
            *p = val;
        }
    }
}

// ---------------- flag barrier: parallel arrivals, ONE poller per CTA -------
// flags: 16 monotonic u32 in one 64B line. Arrival = independent release store
// (no L2 RMW chain). Poll = single thread, 4x v4 volatile loads per iteration.
__device__ __forceinline__ void fbar(unsigned* flags, int cg, unsigned tgt) {
    __syncthreads();   // all CTA stores for this phase issued
    if (threadIdx.x == 0) {
        asm volatile("st.release.gpu.global.u32 [%0], %1;"
                     :: "l"(flags + cg), "r"(tgt) : "memory");
        for (;;) {
            unsigned x0,x1,x2,x3,x4,x5,x6,x7,x8,x9,xa,xb,xc,xd,xe,xf;
            asm volatile("ld.volatile.global.v4.u32 {%0,%1,%2,%3}, [%4];"
                         : "=r"(x0),"=r"(x1),"=r"(x2),"=r"(x3) : "l"(flags));
            asm volatile("ld.volatile.global.v4.u32 {%0,%1,%2,%3}, [%4];"
                         : "=r"(x4),"=r"(x5),"=r"(x6),"=r"(x7) : "l"(flags+4));
            asm volatile("ld.volatile.global.v4.u32 {%0,%1,%2,%3}, [%4];"
                         : "=r"(x8),"=r"(x9),"=r"(xa),"=r"(xb) : "l"(flags+8));
            asm volatile("ld.volatile.global.v4.u32 {%0,%1,%2,%3}, [%4];"
                         : "=r"(xc),"=r"(xd),"=r"(xe),"=r"(xf) : "l"(flags+12));
            unsigned m = min(min(min(x0,x1),min(x2,x3)),
                             min(min(min(x4,x5),min(x6,x7)),
                                 min(min(min(x8,x9),min(xa,xb)),
                                     min(min(xc,xd),min(xe,xf)))));
            if (m >= tgt) break;
        }
        asm volatile("fence.acq_rel.gpu;" ::: "memory");
    }
    __syncthreads();
}

// ---------------- persistent scan: 8 groups x 16 CTAs, 2 batch rows/group ---
__global__ __launch_bounds__(256, 1) void scan_kernel(
    const float* __restrict__ C1, const float* __restrict__ W1,
    const float* __restrict__ a1, const float* __restrict__ taup,
    const float* __restrict__ gamp)
{
    extern __shared__ float sm[];
    float* wC   = sm;                       // 32*32*20 = 20480
    float* wW   = wC + GCOLS*32*WSL;        // 20480
    float* hb   = wW + GCOLS*32*WSL;        // 64*20 = 1280 (2 rows, padded slices)
    float* eb   = hb + 64*WSL;              // 1280
    float* sga  = eb + 64*WSL;              // 32
    float* snorm= sga + GCOLS;              // 2

    const int cta = blockIdx.x;
    const int g   = cta >> 4;               // group = batch pair
    const int cg  = cta & 15;               // CTA in group
    const int tid = threadIdx.x;
    const int mbase = cg*GCOLS;             // col base in [0,512)
    const int b0 = g*2;

    // weights into padded conflict-free slice layout: slice (m*32 + k/16), len 16
    for (int idx = tid; idx < GCOLS*HID; idx += 256) {
        int m = idx >> 9, k = idx & 511;
        int sl = (m*32 + (k>>4))*WSL + (k&15);
        wC[sl] = C1[(size_t)(mbase+m)*HID + k];
        wW[sl] = W1[(size_t)(mbase+m)*HID + k];
    }
    if (tid < GCOLS) sga[tid] = 1.f/(1.f + expf(-a1[mbase+tid]));
    const float tau = taup[0], gam = gamp[0];
    unsigned* flags = g_flagA + g*16;
    __syncthreads();

    const int warp = tid >> 5, lane = tid & 31;   // warp covers 4 cols, lane = k-slice
    const float* wc0 = &wC[((warp*4+0)*32 + lane)*WSL];
    const float* wc1 = &wC[((warp*4+1)*32 + lane)*WSL];
    const float* wc2 = &wC[((warp*4+2)*32 + lane)*WSL];
    const float* wc3 = &wC[((warp*4+3)*32 + lane)*WSL];
    const float* ww0 = &wW[((warp*4+0)*32 + lane)*WSL];
    const float* ww1 = &wW[((warp*4+1)*32 + lane)*WSL];
    const float* ww2 = &wW[((warp*4+2)*32 + lane)*WSL];
    const float* ww3 = &wW[((warp*4+3)*32 + lane)*WSL];
    const float* hs0 = &hb[(lane)*WSL];
    const float* hs1 = &hb[(32+lane)*WSL];
    const float* es0 = &eb[(lane)*WSL];
    const float* es1 = &eb[(32+lane)*WSL];

    const int cloc = warp*4 + (lane & 3);   // this lane's col (owners: lane<4)
    const int col  = mbase + cloc;
    const int hv0i = ((col >> 4))*WSL + (col & 15);       // row0 slice of h
    const int hv1i = ((32 + (col >> 4)))*WSL + (col & 15);

    for (int t = 0; t < T_STEPS; ++t) {
        // per-step operand prefetch (owners only), retires under the GEMM
        float pb00=0.f, pb01=0.f, pb10=0.f, pb11=0.f;
        if (lane < 4) {
            size_t r = ((size_t)t*BATCH + b0)*HID + col;
            pb00 = __ldcg(&g_be0[r]);
            pb01 = __ldcg(&g_be0[r + HID]);
            pb10 = __ldcg(&g_be1[r]);
            pb11 = __ldcg(&g_be1[r + HID]);
        }
        float psc0 = __ldcg(&g_scale1[t*BATCH + b0]);
        float psc1 = __ldcg(&g_scale1[t*BATCH + b0 + 1]);

        // load h (2 rows, 4KB) into padded smem
        {
            const float* src = (t == 0) ? (g_hzero + b0*HID)
                                        : (g_hall + ((size_t)(t-1)*BATCH + b0)*HID);
            float4 v = __ldcg(((const float4*)src) + tid);
            int row = tid >> 7, k4 = (tid & 127)*4;
            *(float4*)&hb[(row*32 + (k4>>4))*WSL + (k4&15)] = v;
        }
        __syncthreads();

        // ---- phase A: P = h @ C1^T (4 cols x 2 rows per warp, 32-way k-split)
        float a00=0,a01=0,a10=0,a11=0,a20=0,a21=0,a30=0,a31=0;
        #pragma unroll
        for (int i = 0; i < 4; i++) {
            float4 x0 = *(const float4*)&hs0[i*4];
            float4 x1 = *(const float4*)&hs1[i*4];
            float4 u0 = *(const float4*)&wc0[i*4];
            float4 u1 = *(const float4*)&wc1[i*4];
            float4 u2 = *(const float4*)&wc2[i*4];
            float4 u3 = *(const float4*)&wc3[i*4];
            a00 += u0.x*x0.x + u0.y*x0.y + u0.z*x0.z + u0.w*x0.w;
            a01 += u0.x*x1.x + u0.y*x1.y + u0.z*x1.z + u0.w*x1.w;
            a10 += u1.x*x0.x + u1.y*x0.y + u1.z*x0.z + u1.w*x0.w;
            a11 += u1.x*x1.x + u1.y*x1.y + u1.z*x1.z + u1.w*x1.w;
            a20 += u2.x*x0.x + u2.y*x0.y + u2.z*x0.z + u2.w*x0.w;
            a21 += u2.x*x1.x + u2.y*x1.y + u2.z*x1.z + u2.w*x1.w;
            a30 += u3.x*x0.x + u3.y*x0.y + u3.z*x0.z + u3.w*x0.w;
            a31 += u3.x*x1.x + u3.y*x1.y + u3.z*x1.z + u3.w*x1.w;
        }
        #pragma unroll
        for (int off = 16; off; off >>= 1) {
            a00 += __shfl_xor_sync(0xffffffffu, a00, off);
            a01 += __shfl_xor_sync(0xffffffffu, a01, off);
            a10 += __shfl_xor_sync(0xffffffffu, a10, off);
            a11 += __shfl_xor_sync(0xffffffffu, a11, off);
            a20 += __shfl_xor_sync(0xffffffffu, a20, off);
            a21 += __shfl_xor_sync(0xffffffffu, a21, off);
            a30 += __shfl_xor_sync(0xffffffffu, a30, off);
            a31 += __shfl_xor_sync(0xffffffffu, a31, off);
        }
        float e0 = 0.f, e1 = 0.f;
        if (lane < 4) {
            float p0 = a00, p1 = a01;
            if (lane == 1) { p0 = a10; p1 = a11; }
            if (lane == 2) { p0 = a20; p1 = a21; }
            if (lane == 3) { p0 = a30; p1 = a31; }
            e0 = pb00 - tanhf(p0)*psc0;
            e1 = pb01 - tanhf(p1)*psc1;
            g_err[b0*HID + col]     = e0;
            g_err[(b0+1)*HID + col] = e1;
        }
        float s0 = e0*e0, s1 = e1*e1;     // non-owners contribute 0
        #pragma unroll
        for (int off = 16; off; off >>= 1) {
            s0 += __shfl_xor_sync(0xffffffffu, s0, off);
            s1 += __shfl_xor_sync(0xffffffffu, s1, off);
        }
        if (lane == 0) {
            g_normp[b0*128     + cg*8 + warp] = s0;
            g_normp[(b0+1)*128 + cg*8 + warp] = s1;
        }
        fbar(flags, cg, 2u*(unsigned)t + 1u);

        // load full error (2 rows) + reduce norm partials
        {
            float4 v = __ldcg(((const float4*)(g_err + b0*HID)) + tid);
            int row = tid >> 7, k4 = (tid & 127)*4;
            *(float4*)&eb[(row*32 + (k4>>4))*WSL + (k4&15)] = v;
        }
        if (warp < 2) {
            float4 v = __ldcg(((const float4*)(g_normp + (b0+warp)*128)) + lane);
            float s = v.x + v.y + v.z + v.w;
            #pragma unroll
            for (int off = 16; off; off >>= 1) s += __shfl_xor_sync(0xffffffffu, s, off);
            if (lane == 0) snorm[warp] = s;
        }
        __syncthreads();

        // ---- phase B: E = err @ W1^T -> h update ----
        float b00=0,b01=0,b10=0,b11=0,b20=0,b21=0,b30=0,b31=0;
        #pragma unroll
        for (int i = 0; i < 4; i++) {
            float4 x0 = *(const float4*)&es0[i*4];
            float4 x1 = *(const float4*)&es1[i*4];
            float4 u0 = *(const float4*)&ww0[i*4];
            float4 u1 = *(const float4*)&ww1[i*4];
            float4 u2 = *(const float4*)&ww2[i*4];
            float4 u3 = *(const float4*)&ww3[i*4];
            b00 += u0.x*x0.x + u0.y*x0.y + u0.z*x0.z + u0.w*x0.w;
            b01 += u0.x*x1.x + u0.y*x1.y + u0.z*x1.z + u0.w*x1.w;
            b10 += u1.x*x0.x + u1.y*x0.y + u1.z*x0.z + u1.w*x0.w;
            b11 += u1.x*x1.x + u1.y*x1.y + u1.z*x1.z + u1.w*x1.w;
            b20 += u2.x*x0.x + u2.y*x0.y + u2.z*x0.z + u2.w*x0.w;
            b21 += u2.x*x1.x + u2.y*x1.y + u2.z*x1.z + u2.w*x1.w;
            b30 += u3.x*x0.x + u3.y*x0.y + u3.z*x0.z + u3.w*x0.w;
            b31 += u3.x*x1.x + u3.y*x1.y + u3.z*x1.z + u3.w*x1.w;
        }
        #pragma unroll
        for (int off = 16; off; off >>= 1) {
            b00 += __shfl_xor_sync(0xffffffffu, b00, off);
            b01 += __shfl_xor_sync(0xffffffffu, b01, off);
            b10 += __shfl_xor_sync(0xffffffffu, b10, off);
            b11 += __shfl_xor_sync(0xffffffffu, b11, off);
            b20 += __shfl_xor_sync(0xffffffffu, b20, off);
            b21 += __shfl_xor_sync(0xffffffffu, b21, off);
            b30 += __shfl_xor_sync(0xffffffffu, b30, off);
            b31 += __shfl_xor_sync(0xffffffffu, b31, off);
        }
        if (lane < 4) {
            float q0 = b00, q1 = b01;
            if (lane == 1) { q0 = b10; q1 = b11; }
            if (lane == 2) { q0 = b20; q1 = b21; }
            if (lane == 3) { q0 = b30; q1 = b31; }
            float rel0 = fminf(sqrtf(snorm[0])/psc0, 4.f);
            float rel1 = fminf(sqrtf(snorm[1])/psc1, 4.f);
            float sur0 = 1.f/(1.f + expf(-(rel0 - tau)/gam));
            float sur1 = 1.f/(1.f + expf(-(rel1 - tau)/gam));
            float hv0 = hb[hv0i];
            float hv1 = hb[hv1i];
            float ih0 = 0.2f*hv0 + 0.6f*pb10 + 0.2f*sur0*q0;
            float ih1 = 0.2f*hv1 + 0.6f*pb11 + 0.2f*sur1*q1;
            float sg  = sga[cloc];
            float gg0 = sur0*sg, gg1 = sur1*sg;
            size_t orow = ((size_t)t*BATCH + b0)*HID + col;
            g_hall[orow]       = hv0*(1.f - gg0) + tanhf(ih0)*gg0;
            g_hall[orow + HID] = hv1*(1.f - gg1) + tanhf(ih1)*gg1;
        }
        fbar(flags, cg, 2u*(unsigned)t + 2u);
    }
}

// ---------------- launch ----------------------------------------------------
extern "C" void kernel_launch(void* const* d_in, const int* in_sizes, int n_in,
                              void* d_out, int out_size)
{
    const float* feats  = (const float*)d_in[0];
    const float* B0     = (const float*)d_in[2];
    const float* C1     = (const float*)d_in[7];
    const float* B1     = (const float*)d_in[8];
    const float* W1     = (const float*)d_in[9];
    const float* a1     = (const float*)d_in[10];
    const float* tau1   = (const float*)d_in[11];
    const float* gam1   = (const float*)d_in[12];
    const float* head_w = (const float*)d_in[13];
    const float* head_b = (const float*)d_in[14];
    float* out = (float*)d_out;

    float *p_xn1, *p_be1, *p_hall;
    cudaGetSymbolAddress((void**)&p_xn1,  g_xn1);
    cudaGetSymbolAddress((void**)&p_be1,  g_be1);
    cudaGetSymbolAddress((void**)&p_hall, g_hall);

    const int SCAN_SMEM = (2*GCOLS*32*WSL + 2*64*WSL + GCOLS + 2 + 30)*4;
    cudaFuncSetAttribute(scan_kernel, cudaFuncAttributeMaxDynamicSharedMemorySize, SCAN_SMEM);

    // launch #0: fused zero + xnorm0 + be0 GEMM
    fused_be0_kernel<<<NROWS/64, 256>>>(feats, B0);
    // launch #1
    xnorm1_kernel<<<(NROWS*32)/256, 256>>>();
    // launch #2: be1 = xn1 @ B1^T
    dim3 g1(HID/64, NROWS/64);
    sgemm_nt<<<g1, 256>>>(p_xn1, HID, B1, HID, p_be1, HID, HID, 0, nullptr, 0);
    // launch #3: the scan (ncu capture target)
    scan_kernel<<<SCAN_CTAS, 256, SCAN_SMEM>>>(C1, W1, a1, tau1, gam1);
    // head
    dim3 gh(NCLS/64, NROWS/64);
    sgemm_nt<<<gh, 256>>>(p_hall, HID, head_w,       2*HID, out, NCLS, HID, 0, nullptr, 1);
    sgemm_nt<<<gh, 256>>>(p_be1,  HID, head_w + HID, 2*HID, out, NCLS, HID, 1, head_b, 1);
}

// round 15
// speedup vs baseline: 5.6456x; 5.6456x over previous
#include <cuda_runtime.h>
#include <math.h>

#define T_STEPS 1000
#define BATCH   16
#define MEL     80
#define HID     512
#define NCLS    64
#define NROWS   (T_STEPS*BATCH)      // 16000

#define NGROUPS   8
#define GCTAS     16                 // CTAs per group (sync domain)
#define SCAN_CTAS (NGROUPS*GCTAS)    // 128
#define GCOLS     32                 // cols per CTA
#define WSL       20                 // padded k-slice stride (16 data + 4 pad floats)

// ---------------- scratch (device globals; no allocation allowed) ----------
__device__ float    g_be0[NROWS*HID];
__device__ float    g_be1[NROWS*HID];
__device__ float    g_hall[NROWS*HID];
__device__ float    g_scale1[NROWS];
__device__ float    g_err[BATCH*HID];
__device__ float    g_normp[BATCH*128];   // [b][cta_in_group*8 + warp]
__device__ float    g_hzero[BATCH*HID];
__device__ unsigned g_ctr2[NGROUPS*2048]; // per-group per-step counters

__device__ __forceinline__ float clip1(float v) {
    return fminf(fmaxf(v, -1.f), 1.f);
}

// ---------------- fused: zero scratch + xnorm0 + be0 GEMM ------------------
__global__ __launch_bounds__(256) void fused_be0_kernel(
    const float* __restrict__ feats, const float* __restrict__ B0)
{
    __shared__ float xs[64][80];

    const int tid  = threadIdx.x;
    const int warp = tid >> 5, lane = tid & 31;
    const int r_base = blockIdx.x*64 + warp*8;

    if (blockIdx.x == 0) {
        for (int i = tid; i < NGROUPS*2048; i += 256) g_ctr2[i] = 0u;
        for (int i = tid; i < BATCH*HID; i += 256) g_hzero[i] = 0.f;
    }

    #pragma unroll
    for (int rr = 0; rr < 8; rr++) {
        int r = r_base + rr;
        int t = r >> 4, b = r & 15;
        const float* row = feats + ((size_t)b*T_STEPS + t)*MEL;
        float v0 = row[lane];
        float v1 = row[lane+32];
        float v2 = (lane < 16) ? row[lane+64] : 0.f;
        float s = v0*v0 + v1*v1 + v2*v2;
        #pragma unroll
        for (int off = 16; off; off >>= 1) s += __shfl_xor_sync(0xffffffffu, s, off);
        float inv = 1.f/fmaxf(sqrtf(s), 1e-6f);
        int lr = warp*8 + rr;
        xs[lr][lane]    = clip1(v0*inv);
        xs[lr][lane+32] = clip1(v1*inv);
        if (lane < 16) xs[lr][lane+64] = clip1(v2*inv);
    }
    __syncwarp();

    #pragma unroll 1
    for (int q = 0; q < 4; q++) {
        int c0 = q*128 + lane*4;
        float acc[8][4];
        #pragma unroll
        for (int rr = 0; rr < 8; rr++)
            #pragma unroll
            for (int j = 0; j < 4; j++) acc[rr][j] = 0.f;

        for (int kc = 0; kc < 20; kc++) {
            float4 b40 = *(const float4*)(B0 + (size_t)(c0+0)*MEL + kc*4);
            float4 b41 = *(const float4*)(B0 + (size_t)(c0+1)*MEL + kc*4);
            float4 b42 = *(const float4*)(B0 + (size_t)(c0+2)*MEL + kc*4);
            float4 b43 = *(const float4*)(B0 + (size_t)(c0+3)*MEL + kc*4);
            #pragma unroll
            for (int rr = 0; rr < 8; rr++) {
                float4 x4 = *(const float4*)&xs[warp*8+rr][kc*4];
                acc[rr][0] += x4.x*b40.x + x4.y*b40.y + x4.z*b40.z + x4.w*b40.w;
                acc[rr][1] += x4.x*b41.x + x4.y*b41.y + x4.z*b41.z + x4.w*b41.w;
                acc[rr][2] += x4.x*b42.x + x4.y*b42.y + x4.z*b42.z + x4.w*b42.w;
                acc[rr][3] += x4.x*b43.x + x4.y*b43.y + x4.z*b43.z + x4.w*b43.w;
            }
        }
        #pragma unroll
        for (int rr = 0; rr < 8; rr++) {
            int r = r_base + rr;
            *(float4*)&g_be0[(size_t)r*HID + c0] =
                make_float4(acc[rr][0], acc[rr][1], acc[rr][2], acc[rr][3]);
        }
    }
}

// ---------------- scale-only for cell1 input (be0 row norms) ----------------
__global__ void scale1_kernel() {
    int w    = (blockIdx.x*blockDim.x + threadIdx.x) >> 5;
    int lane = threadIdx.x & 31;
    if (w >= NROWS) return;
    const float4* row = (const float4*)(g_be0 + (size_t)w*HID);
    float s = 0.f;
    #pragma unroll
    for (int i = 0; i < 4; i++) {
        float4 v = row[lane + 32*i];
        s += v.x*v.x + v.y*v.y + v.z*v.z + v.w*v.w;
    }
    #pragma unroll
    for (int off = 16; off; off >>= 1) s += __shfl_xor_sync(0xffffffffu, s, off);
    if (lane == 0) g_scale1[w] = fmaxf(sqrtf(s), 1e-6f);
}

// ---------------- tiled SGEMM: C = normclip(A)(M,K) @ W(N,K)^T --------------
// If scaleA != nullptr, A rows are divided by scaleA[row] and clipped to ±1.
__global__ __launch_bounds__(256) void sgemm_nt(
    const float* __restrict__ A, int lda,
    const float* __restrict__ W, int ldw,
    float*       __restrict__ C, int ldc,
    int K, const float* __restrict__ scaleA)
{
    __shared__ float As[16][64];
    __shared__ float Ws[16][64];
    int bm = blockIdx.y*64, bn = blockIdx.x*64;
    int tid = threadIdx.x;
    int lr  = tid >> 2;
    int kq  = (tid & 3)*4;
    int tx  = tid & 15, ty = tid >> 4;
    float acc[4][4];
    #pragma unroll
    for (int i=0;i<4;i++)
        #pragma unroll
        for (int j=0;j<4;j++) acc[i][j]=0.f;

    float inv = 1.f;
    if (scaleA) inv = 1.f/scaleA[bm+lr];

    for (int k0 = 0; k0 < K; k0 += 16) {
        float4 av = *(const float4*)(A + (size_t)(bm+lr)*lda + k0 + kq);
        if (scaleA) {
            av.x = clip1(av.x*inv); av.y = clip1(av.y*inv);
            av.z = clip1(av.z*inv); av.w = clip1(av.w*inv);
        }
        float4 wv = *(const float4*)(W + (size_t)(bn+lr)*ldw + k0 + kq);
        As[kq+0][lr]=av.x; As[kq+1][lr]=av.y; As[kq+2][lr]=av.z; As[kq+3][lr]=av.w;
        Ws[kq+0][lr]=wv.x; Ws[kq+1][lr]=wv.y; Ws[kq+2][lr]=wv.z; Ws[kq+3][lr]=wv.w;
        __syncthreads();
        #pragma unroll
        for (int k = 0; k < 16; k++) {
            float4 a4 = *(float4*)&As[k][ty*4];
            float4 w4 = *(float4*)&Ws[k][tx*4];
            float ar[4] = {a4.x, a4.y, a4.z, a4.w};
            float wr[4] = {w4.x, w4.y, w4.z, w4.w};
            #pragma unroll
            for (int i=0;i<4;i++)
                #pragma unroll
                for (int j=0;j<4;j++) acc[i][j] += ar[i]*wr[j];
        }
        __syncthreads();
    }
    #pragma unroll
    for (int i = 0; i < 4; i++) {
        int r = bm + ty*4 + i;
        #pragma unroll
        for (int j = 0; j < 4; j++) {
            int cidx = bn + tx*4 + j;
            C[(size_t)r*ldc + cidx] = acc[i][j];
        }
    }
}

// ---------------- fused head: out = hall@hw0^T + be1@hw1^T + bias -----------
// W is (NCLS, 2*HID); stage 0 uses cols [0,HID), stage 1 cols [HID,2*HID).
__global__ __launch_bounds__(256) void head_kernel(
    const float* __restrict__ A1, const float* __restrict__ A2,
    const float* __restrict__ W, const float* __restrict__ bias,
    float* __restrict__ C)
{
    __shared__ float As[16][64];
    __shared__ float Ws[16][64];
    int bm = blockIdx.y*64;
    int tid = threadIdx.x;
    int lr  = tid >> 2;
    int kq  = (tid & 3)*4;
    int tx  = tid & 15, ty = tid >> 4;
    float acc[4][4];
    #pragma unroll
    for (int i=0;i<4;i++)
        #pragma unroll
        for (int j=0;j<4;j++) acc[i][j]=0.f;

    #pragma unroll 1
    for (int s = 0; s < 2; s++) {
        const float* A = s ? A2 : A1;
        const int wofs = s*HID;
        for (int k0 = 0; k0 < HID; k0 += 16) {
            float4 av = *(const float4*)(A + (size_t)(bm+lr)*HID + k0 + kq);
            float4 wv = *(const float4*)(W + (size_t)lr*(2*HID) + wofs + k0 + kq);
            As[kq+0][lr]=av.x; As[kq+1][lr]=av.y; As[kq+2][lr]=av.z; As[kq+3][lr]=av.w;
            Ws[kq+0][lr]=wv.x; Ws[kq+1][lr]=wv.y; Ws[kq+2][lr]=wv.z; Ws[kq+3][lr]=wv.w;
            __syncthreads();
            #pragma unroll
            for (int k = 0; k < 16; k++) {
                float4 a4 = *(float4*)&As[k][ty*4];
                float4 w4 = *(float4*)&Ws[k][tx*4];
                float ar[4] = {a4.x, a4.y, a4.z, a4.w};
                float wr[4] = {w4.x, w4.y, w4.z, w4.w};
                #pragma unroll
                for (int i=0;i<4;i++)
                    #pragma unroll
                    for (int j=0;j<4;j++) acc[i][j] += ar[i]*wr[j];
            }
            __syncthreads();
        }
    }
    #pragma unroll
    for (int i = 0; i < 4; i++) {
        int r = bm + ty*4 + i;
        int orow = (r & 15)*T_STEPS + (r >> 4);   // (b, t) remap
        #pragma unroll
        for (int j = 0; j < 4; j++) {
            int cidx = tx*4 + j;
            C[(size_t)orow*NCLS + cidx] = acc[i][j] + bias[cidx];
        }
    }
}

// ---------------- group barrier: 16 arrivals, release/acquire (PROVEN) ------
__device__ __forceinline__ void gbar(unsigned* c) {
    __syncthreads();
    if (threadIdx.x == 0) {
        asm volatile("red.release.gpu.global.add.u32 [%0], 1;" :: "l"(c) : "memory");
        unsigned v;
        do {
            asm volatile("ld.acquire.gpu.global.u32 %0, [%1];" : "=r"(v) : "l"(c) : "memory");
        } while (v < GCTAS);
    }
    __syncthreads();
}

// ---------------- persistent scan: 8 groups x 16 CTAs, 2 batch rows/group ---
__global__ __launch_bounds__(256, 1) void scan_kernel(
    const float* __restrict__ C1, const float* __restrict__ W1,
    const float* __restrict__ a1, const float* __restrict__ taup,
    const float* __restrict__ gamp)
{
    extern __shared__ float sm[];
    float* wC   = sm;                       // 32*32*20 = 20480
    float* wW   = wC + GCOLS*32*WSL;        // 20480
    float* hb   = wW + GCOLS*32*WSL;        // 64*20 = 1280 (2 rows, padded slices)
    float* eb   = hb + 64*WSL;              // 1280
    float* sga  = eb + 64*WSL;              // 32
    float* snorm= sga + GCOLS;              // 2

    const int cta = blockIdx.x;
    const int g   = cta >> 4;               // group = batch pair
    const int cg  = cta & 15;               // CTA in group
    const int tid = threadIdx.x;
    const int mbase = cg*GCOLS;             // col base in [0,512)
    const int b0 = g*2;

    // weights into padded conflict-free slice layout: slice (m*32 + k/16), len 16
    for (int idx = tid; idx < GCOLS*HID; idx += 256) {
        int m = idx >> 9, k = idx & 511;
        int sl = (m*32 + (k>>4))*WSL + (k&15);
        wC[sl] = C1[(size_t)(mbase+m)*HID + k];
        wW[sl] = W1[(size_t)(mbase+m)*HID + k];
    }
    if (tid < GCOLS) sga[tid] = 1.f/(1.f + expf(-a1[mbase+tid]));
    const float tau = taup[0], gam = gamp[0];
    unsigned* ctr = g_ctr2 + g*2048;
    __syncthreads();

    const int warp = tid >> 5, lane = tid & 31;   // warp covers 4 cols, lane = k-slice
    const float* wc0 = &wC[((warp*4+0)*32 + lane)*WSL];
    const float* wc1 = &wC[((warp*4+1)*32 + lane)*WSL];
    const float* wc2 = &wC[((warp*4+2)*32 + lane)*WSL];
    const float* wc3 = &wC[((warp*4+3)*32 + lane)*WSL];
    const float* ww0 = &wW[((warp*4+0)*32 + lane)*WSL];
    const float* ww1 = &wW[((warp*4+1)*32 + lane)*WSL];
    const float* ww2 = &wW[((warp*4+2)*32 + lane)*WSL];
    const float* ww3 = &wW[((warp*4+3)*32 + lane)*WSL];
    const float* hs0 = &hb[(lane)*WSL];
    const float* hs1 = &hb[(32+lane)*WSL];
    const float* es0 = &eb[(lane)*WSL];
    const float* es1 = &eb[(32+lane)*WSL];

    const int cloc = warp*4 + (lane & 3);   // this lane's col (owners: lane<4)
    const int col  = mbase + cloc;
    const int hv0i = ((col >> 4))*WSL + (col & 15);       // row0 slice of h
    const int hv1i = ((32 + (col >> 4)))*WSL + (col & 15);

    for (int t = 0; t < T_STEPS; ++t) {
        // per-step operand prefetch (owners only), retires under the GEMM
        float pb00=0.f, pb01=0.f, pb10=0.f, pb11=0.f;
        if (lane < 4) {
            size_t r = ((size_t)t*BATCH + b0)*HID + col;
            pb00 = __ldcg(&g_be0[r]);
            pb01 = __ldcg(&g_be0[r + HID]);
            pb10 = __ldcg(&g_be1[r]);
            pb11 = __ldcg(&g_be1[r + HID]);
        }
        float psc0 = __ldcg(&g_scale1[t*BATCH + b0]);
        float psc1 = __ldcg(&g_scale1[t*BATCH + b0 + 1]);

        // load h (2 rows, 4KB) into padded smem
        {
            const float* src = (t == 0) ? (g_hzero + b0*HID)
                                        : (g_hall + ((size_t)(t-1)*BATCH + b0)*HID);
            float4 v = __ldcg(((const float4*)src) + tid);
            int row = tid >> 7, k4 = (tid & 127)*4;
            *(float4*)&hb[(row*32 + (k4>>4))*WSL + (k4&15)] = v;
        }
        __syncthreads();

        // ---- phase A: P = h @ C1^T (4 cols x 2 rows per warp, 32-way k-split)
        float a00=0,a01=0,a10=0,a11=0,a20=0,a21=0,a30=0,a31=0;
        #pragma unroll
        for (int i = 0; i < 4; i++) {
            float4 x0 = *(const float4*)&hs0[i*4];
            float4 x1 = *(const float4*)&hs1[i*4];
            float4 u0 = *(const float4*)&wc0[i*4];
            float4 u1 = *(const float4*)&wc1[i*4];
            float4 u2 = *(const float4*)&wc2[i*4];
            float4 u3 = *(const float4*)&wc3[i*4];
            a00 += u0.x*x0.x + u0.y*x0.y + u0.z*x0.z + u0.w*x0.w;
            a01 += u0.x*x1.x + u0.y*x1.y + u0.z*x1.z + u0.w*x1.w;
            a10 += u1.x*x0.x + u1.y*x0.y + u1.z*x0.z + u1.w*x0.w;
            a11 += u1.x*x1.x + u1.y*x1.y + u1.z*x1.z + u1.w*x1.w;
            a20 += u2.x*x0.x + u2.y*x0.y + u2.z*x0.z + u2.w*x0.w;
            a21 += u2.x*x1.x + u2.y*x1.y + u2.z*x1.z + u2.w*x1.w;
            a30 += u3.x*x0.x + u3.y*x0.y + u3.z*x0.z + u3.w*x0.w;
            a31 += u3.x*x1.x + u3.y*x1.y + u3.z*x1.z + u3.w*x1.w;
        }
        #pragma unroll
        for (int off = 16; off; off >>= 1) {
            a00 += __shfl_xor_sync(0xffffffffu, a00, off);
            a01 += __shfl_xor_sync(0xffffffffu, a01, off);
            a10 += __shfl_xor_sync(0xffffffffu, a10, off);
            a11 += __shfl_xor_sync(0xffffffffu, a11, off);
            a20 += __shfl_xor_sync(0xffffffffu, a20, off);
            a21 += __shfl_xor_sync(0xffffffffu, a21, off);
            a30 += __shfl_xor_sync(0xffffffffu, a30, off);
            a31 += __shfl_xor_sync(0xffffffffu, a31, off);
        }
        float e0 = 0.f, e1 = 0.f;
        if (lane < 4) {
            float p0 = a00, p1 = a01;
            if (lane == 1) { p0 = a10; p1 = a11; }
            if (lane == 2) { p0 = a20; p1 = a21; }
            if (lane == 3) { p0 = a30; p1 = a31; }
            e0 = pb00 - tanhf(p0)*psc0;
            e1 = pb01 - tanhf(p1)*psc1;
            g_err[b0*HID + col]     = e0;
            g_err[(b0+1)*HID + col] = e1;
        }
        float s0 = e0*e0, s1 = e1*e1;     // non-owners contribute 0
        #pragma unroll
        for (int off = 16; off; off >>= 1) {
            s0 += __shfl_xor_sync(0xffffffffu, s0, off);
            s1 += __shfl_xor_sync(0xffffffffu, s1, off);
        }
        if (lane == 0) {
            g_normp[b0*128     + cg*8 + warp] = s0;
            g_normp[(b0+1)*128 + cg*8 + warp] = s1;
        }
        gbar(ctr + 2*t);

        // load full error (2 rows) + reduce norm partials
        {
            float4 v = __ldcg(((const float4*)(g_err + b0*HID)) + tid);
            int row = tid >> 7, k4 = (tid & 127)*4;
            *(float4*)&eb[(row*32 + (k4>>4))*WSL + (k4&15)] = v;
        }
        if (warp < 2) {
            float4 v = __ldcg(((const float4*)(g_normp + (b0+warp)*128)) + lane);
            float s = v.x + v.y + v.z + v.w;
            #pragma unroll
            for (int off = 16; off; off >>= 1) s += __shfl_xor_sync(0xffffffffu, s, off);
            if (lane == 0) snorm[warp] = s;
        }
        __syncthreads();

        // ---- phase B: E = err @ W1^T -> h update ----
        float b00=0,b01=0,b10=0,b11=0,b20=0,b21=0,b30=0,b31=0;
        #pragma unroll
        for (int i = 0; i < 4; i++) {
            float4 x0 = *(const float4*)&es0[i*4];
            float4 x1 = *(const float4*)&es1[i*4];
            float4 u0 = *(const float4*)&ww0[i*4];
            float4 u1 = *(const float4*)&ww1[i*4];
            float4 u2 = *(const float4*)&ww2[i*4];
            float4 u3 = *(const float4*)&ww3[i*4];
            b00 += u0.x*x0.x + u0.y*x0.y + u0.z*x0.z + u0.w*x0.w;
            b01 += u0.x*x1.x + u0.y*x1.y + u0.z*x1.z + u0.w*x1.w;
            b10 += u1.x*x0.x + u1.y*x0.y + u1.z*x0.z + u1.w*x0.w;
            b11 += u1.x*x1.x + u1.y*x1.y + u1.z*x1.z + u1.w*x1.w;
            b20 += u2.x*x0.x + u2.y*x0.y + u2.z*x0.z + u2.w*x0.w;
            b21 += u2.x*x1.x + u2.y*x1.y + u2.z*x1.z + u2.w*x1.w;
            b30 += u3.x*x0.x + u3.y*x0.y + u3.z*x0.z + u3.w*x0.w;
            b31 += u3.x*x1.x + u3.y*x1.y + u3.z*x1.z + u3.w*x1.w;
        }
        #pragma unroll
        for (int off = 16; off; off >>= 1) {
            b00 += __shfl_xor_sync(0xffffffffu, b00, off);
            b01 += __shfl_xor_sync(0xffffffffu, b01, off);
            b10 += __shfl_xor_sync(0xffffffffu, b10, off);
            b11 += __shfl_xor_sync(0xffffffffu, b11, off);
            b20 += __shfl_xor_sync(0xffffffffu, b20, off);
            b21 += __shfl_xor_sync(0xffffffffu, b21, off);
            b30 += __shfl_xor_sync(0xffffffffu, b30, off);
            b31 += __shfl_xor_sync(0xffffffffu, b31, off);
        }
        if (lane < 4) {
            float q0 = b00, q1 = b01;
            if (lane == 1) { q0 = b10; q1 = b11; }
            if (lane == 2) { q0 = b20; q1 = b21; }
            if (lane == 3) { q0 = b30; q1 = b31; }
            float rel0 = fminf(sqrtf(snorm[0])/psc0, 4.f);
            float rel1 = fminf(sqrtf(snorm[1])/psc1, 4.f);
            float sur0 = 1.f/(1.f + expf(-(rel0 - tau)/gam));
            float sur1 = 1.f/(1.f + expf(-(rel1 - tau)/gam));
            float hv0 = hb[hv0i];
            float hv1 = hb[hv1i];
            float ih0 = 0.2f*hv0 + 0.6f*pb10 + 0.2f*sur0*q0;
            float ih1 = 0.2f*hv1 + 0.6f*pb11 + 0.2f*sur1*q1;
            float sg  = sga[cloc];
            float gg0 = sur0*sg, gg1 = sur1*sg;
            size_t orow = ((size_t)t*BATCH + b0)*HID + col;
            g_hall[orow]       = hv0*(1.f - gg0) + tanhf(ih0)*gg0;
            g_hall[orow + HID] = hv1*(1.f - gg1) + tanhf(ih1)*gg1;
        }
        gbar(ctr + 2*t + 1);
    }
}

// ---------------- launch ----------------------------------------------------
extern "C" void kernel_launch(void* const* d_in, const int* in_sizes, int n_in,
                              void* d_out, int out_size)
{
    const float* feats  = (const float*)d_in[0];
    const float* B0     = (const float*)d_in[2];
    const float* C1     = (const float*)d_in[7];
    const float* B1     = (const float*)d_in[8];
    const float* W1     = (const float*)d_in[9];
    const float* a1     = (const float*)d_in[10];
    const float* tau1   = (const float*)d_in[11];
    const float* gam1   = (const float*)d_in[12];
    const float* head_w = (const float*)d_in[13];
    const float* head_b = (const float*)d_in[14];
    float* out = (float*)d_out;

    float *p_be0, *p_be1, *p_hall, *p_scale1;
    cudaGetSymbolAddress((void**)&p_be0,    g_be0);
    cudaGetSymbolAddress((void**)&p_be1,    g_be1);
    cudaGetSymbolAddress((void**)&p_hall,   g_hall);
    cudaGetSymbolAddress((void**)&p_scale1, g_scale1);

    const int SCAN_SMEM = (2*GCOLS*32*WSL + 2*64*WSL + GCOLS + 2 + 30)*4;
    cudaFuncSetAttribute(scan_kernel, cudaFuncAttributeMaxDynamicSharedMemorySize, SCAN_SMEM);

    // launch #0: fused zero + xnorm0 + be0 GEMM
    fused_be0_kernel<<<NROWS/64, 256>>>(feats, B0);
    // launch #1: row norms of be0
    scale1_kernel<<<(NROWS*32)/256, 256>>>();
    // launch #2: be1 = normclip(be0) @ B1^T  (normalization fused into A-load)
    dim3 g1(HID/64, NROWS/64);
    sgemm_nt<<<g1, 256>>>(p_be0, HID, B1, HID, p_be1, HID, HID, p_scale1);
    // launch #3: the scan (ncu capture target) — byte-identical to R7 winner
    scan_kernel<<<SCAN_CTAS, 256, SCAN_SMEM>>>(C1, W1, a1, tau1, gam1);
    // launch #4: fused head (both halves + bias, one pass)
    dim3 gh(1, NROWS/64);
    head_kernel<<<gh, 256>>>(p_hall, p_be1, head_w, head_b, out);
}

// round 16
// speedup vs baseline: 5.6965x; 1.0090x over previous
#include <cuda_runtime.h>
#include <math.h>

#define T_STEPS 1000
#define BATCH   16
#define MEL     80
#define HID     512
#define NCLS    64
#define NROWS   (T_STEPS*BATCH)      // 16000

#define NGROUPS   8
#define GCTAS     16                 // CTAs per group (sync domain)
#define SCAN_CTAS (NGROUPS*GCTAS)    // 128
#define GCOLS     32                 // cols per CTA
#define WSL       20                 // padded k-slice stride (16 data + 4 pad floats)

// ---------------- scratch (device globals; no allocation allowed) ----------
__device__ float    g_be0[NROWS*HID];
__device__ float    g_xn1[NROWS*HID];
__device__ float    g_be1[NROWS*HID];
__device__ float    g_hall[NROWS*HID];
__device__ float    g_scale1[NROWS];
__device__ float    g_err[BATCH*HID];
__device__ float    g_normp[BATCH*128];   // [b][cta_in_group*8 + warp]
__device__ float    g_hzero[BATCH*HID];
__device__ unsigned g_ctr2[NGROUPS*2048]; // per-group per-step counters

__device__ __forceinline__ float clip1(float v) {
    return fminf(fmaxf(v, -1.f), 1.f);
}

// ---------------- fused: zero scratch + xnorm0 + be0 GEMM ------------------
__global__ __launch_bounds__(256) void fused_be0_kernel(
    const float* __restrict__ feats, const float* __restrict__ B0)
{
    __shared__ float xs[64][80];

    const int tid  = threadIdx.x;
    const int warp = tid >> 5, lane = tid & 31;
    const int r_base = blockIdx.x*64 + warp*8;

    if (blockIdx.x == 0) {
        for (int i = tid; i < NGROUPS*2048; i += 256) g_ctr2[i] = 0u;
        for (int i = tid; i < BATCH*HID; i += 256) g_hzero[i] = 0.f;
    }

    #pragma unroll
    for (int rr = 0; rr < 8; rr++) {
        int r = r_base + rr;
        int t = r >> 4, b = r & 15;
        const float* row = feats + ((size_t)b*T_STEPS + t)*MEL;
        float v0 = row[lane];
        float v1 = row[lane+32];
        float v2 = (lane < 16) ? row[lane+64] : 0.f;
        float s = v0*v0 + v1*v1 + v2*v2;
        #pragma unroll
        for (int off = 16; off; off >>= 1) s += __shfl_xor_sync(0xffffffffu, s, off);
        float inv = 1.f/fmaxf(sqrtf(s), 1e-6f);
        int lr = warp*8 + rr;
        xs[lr][lane]    = clip1(v0*inv);
        xs[lr][lane+32] = clip1(v1*inv);
        if (lane < 16) xs[lr][lane+64] = clip1(v2*inv);
    }
    __syncwarp();

    #pragma unroll 1
    for (int q = 0; q < 4; q++) {
        int c0 = q*128 + lane*4;
        float acc[8][4];
        #pragma unroll
        for (int rr = 0; rr < 8; rr++)
            #pragma unroll
            for (int j = 0; j < 4; j++) acc[rr][j] = 0.f;

        for (int kc = 0; kc < 20; kc++) {
            float4 b40 = *(const float4*)(B0 + (size_t)(c0+0)*MEL + kc*4);
            float4 b41 = *(const float4*)(B0 + (size_t)(c0+1)*MEL + kc*4);
            float4 b42 = *(const float4*)(B0 + (size_t)(c0+2)*MEL + kc*4);
            float4 b43 = *(const float4*)(B0 + (size_t)(c0+3)*MEL + kc*4);
            #pragma unroll
            for (int rr = 0; rr < 8; rr++) {
                float4 x4 = *(const float4*)&xs[warp*8+rr][kc*4];
                acc[rr][0] += x4.x*b40.x + x4.y*b40.y + x4.z*b40.z + x4.w*b40.w;
                acc[rr][1] += x4.x*b41.x + x4.y*b41.y + x4.z*b41.z + x4.w*b41.w;
                acc[rr][2] += x4.x*b42.x + x4.y*b42.y + x4.z*b42.z + x4.w*b42.w;
                acc[rr][3] += x4.x*b43.x + x4.y*b43.y + x4.z*b43.z + x4.w*b43.w;
            }
        }
        #pragma unroll
        for (int rr = 0; rr < 8; rr++) {
            int r = r_base + rr;
            *(float4*)&g_be0[(size_t)r*HID + c0] =
                make_float4(acc[rr][0], acc[rr][1], acc[rr][2], acc[rr][3]);
        }
    }
}

// ---------------- x_norm + scale for cell1 input (be0) ---------------------
__global__ void xnorm1_kernel() {
    int w    = (blockIdx.x*blockDim.x + threadIdx.x) >> 5;
    int lane = threadIdx.x & 31;
    if (w >= NROWS) return;
    const float4* row = (const float4*)(g_be0 + (size_t)w*HID);
    float4 v[4];
    float s = 0.f;
    #pragma unroll
    for (int i = 0; i < 4; i++) {
        v[i] = row[lane + 32*i];
        s += v[i].x*v[i].x + v[i].y*v[i].y + v[i].z*v[i].z + v[i].w*v[i].w;
    }
    #pragma unroll
    for (int off = 16; off; off >>= 1) s += __shfl_xor_sync(0xffffffffu, s, off);
    float sc = fmaxf(sqrtf(s), 1e-6f);
    if (lane == 0) g_scale1[w] = sc;
    float inv = 1.f/sc;
    float4* o = (float4*)(g_xn1 + (size_t)w*HID);
    #pragma unroll
    for (int i = 0; i < 4; i++) {
        float4 u = v[i];
        u.x = clip1(u.x*inv);
        u.y = clip1(u.y*inv);
        u.z = clip1(u.z*inv);
        u.w = clip1(u.w*inv);
        o[lane + 32*i] = u;
    }
}

// ---------------- 128x64 tiled SGEMM: C = A(M,K) @ W(N,K)^T ------------------
// 256 threads, 8x4 microtile, BK=16. Requires M%128==0, N%64==0, K%16==0.
__global__ __launch_bounds__(256) void sgemm128(
    const float* __restrict__ A, int lda,
    const float* __restrict__ W, int ldw,
    float*       __restrict__ C, int ldc,
    int K, int accumulate, const float* __restrict__ bias, int remap)
{
    __shared__ float As[16][128];
    __shared__ float Ws[16][64];
    const int bm = blockIdx.y*128, bn = blockIdx.x*64;
    const int tid = threadIdx.x;
    const int ar  = tid >> 1,  akq = (tid & 1)*8;   // A loader: 2 float4/thread
    const int br  = tid >> 2,  bkq = (tid & 3)*4;   // W loader: 1 float4/thread
    const int tx  = tid & 15,  ty  = tid >> 4;      // 4 cols x 8 rows per thread
    float acc[8][4];
    #pragma unroll
    for (int i = 0; i < 8; i++)
        #pragma unroll
        for (int j = 0; j < 4; j++) acc[i][j] = 0.f;

    for (int k0 = 0; k0 < K; k0 += 16) {
        float4 a0 = *(const float4*)(A + (size_t)(bm+ar)*lda + k0 + akq);
        float4 a1 = *(const float4*)(A + (size_t)(bm+ar)*lda + k0 + akq + 4);
        float4 wv = *(const float4*)(W + (size_t)(bn+br)*ldw + k0 + bkq);
        As[akq+0][ar]=a0.x; As[akq+1][ar]=a0.y; As[akq+2][ar]=a0.z; As[akq+3][ar]=a0.w;
        As[akq+4][ar]=a1.x; As[akq+5][ar]=a1.y; As[akq+6][ar]=a1.z; As[akq+7][ar]=a1.w;
        Ws[bkq+0][br]=wv.x; Ws[bkq+1][br]=wv.y; Ws[bkq+2][br]=wv.z; Ws[bkq+3][br]=wv.w;
        __syncthreads();
        #pragma unroll
        for (int k = 0; k < 16; k++) {
            float4 aA = *(float4*)&As[k][ty*8];
            float4 aB = *(float4*)&As[k][ty*8 + 4];
            float4 w4 = *(float4*)&Ws[k][tx*4];
            float arr[8] = {aA.x, aA.y, aA.z, aA.w, aB.x, aB.y, aB.z, aB.w};
            float wrr[4] = {w4.x, w4.y, w4.z, w4.w};
            #pragma unroll
            for (int i = 0; i < 8; i++)
                #pragma unroll
                for (int j = 0; j < 4; j++) acc[i][j] += arr[i]*wrr[j];
        }
        __syncthreads();
    }
    #pragma unroll
    for (int i = 0; i < 8; i++) {
        int r = bm + ty*8 + i;
        int orow = remap ? ((r & 15)*T_STEPS + (r >> 4)) : r;
        #pragma unroll
        for (int j = 0; j < 4; j++) {
            int cidx = bn + tx*4 + j;
            float val = acc[i][j];
            if (bias) val += bias[cidx];
            float* p = C + (size_t)orow*ldc + cidx;
            if (accumulate) val += *p;
            *p = val;
        }
    }
}

// ---------------- group barrier: 16 arrivals, release/acquire (PROVEN) ------
__device__ __forceinline__ void gbar(unsigned* c) {
    __syncthreads();
    if (threadIdx.x == 0) {
        asm volatile("red.release.gpu.global.add.u32 [%0], 1;" :: "l"(c) : "memory");
        unsigned v;
        do {
            asm volatile("ld.acquire.gpu.global.u32 %0, [%1];" : "=r"(v) : "l"(c) : "memory");
        } while (v < GCTAS);
    }
    __syncthreads();
}

// ---------------- persistent scan: 8 groups x 16 CTAs, 2 batch rows/group ---
__global__ __launch_bounds__(256, 1) void scan_kernel(
    const float* __restrict__ C1, const float* __restrict__ W1,
    const float* __restrict__ a1, const float* __restrict__ taup,
    const float* __restrict__ gamp)
{
    extern __shared__ float sm[];
    float* wC   = sm;                       // 32*32*20 = 20480
    float* wW   = wC + GCOLS*32*WSL;        // 20480
    float* hb   = wW + GCOLS*32*WSL;        // 64*20 = 1280 (2 rows, padded slices)
    float* eb   = hb + 64*WSL;              // 1280
    float* sga  = eb + 64*WSL;              // 32
    float* snorm= sga + GCOLS;              // 2

    const int cta = blockIdx.x;
    const int g   = cta >> 4;               // group = batch pair
    const int cg  = cta & 15;               // CTA in group
    const int tid = threadIdx.x;
    const int mbase = cg*GCOLS;             // col base in [0,512)
    const int b0 = g*2;

    // weights into padded conflict-free slice layout: slice (m*32 + k/16), len 16
    for (int idx = tid; idx < GCOLS*HID; idx += 256) {
        int m = idx >> 9, k = idx & 511;
        int sl = (m*32 + (k>>4))*WSL + (k&15);
        wC[sl] = C1[(size_t)(mbase+m)*HID + k];
        wW[sl] = W1[(size_t)(mbase+m)*HID + k];
    }
    if (tid < GCOLS) sga[tid] = 1.f/(1.f + expf(-a1[mbase+tid]));
    const float tau = taup[0], gam = gamp[0];
    unsigned* ctr = g_ctr2 + g*2048;
    __syncthreads();

    const int warp = tid >> 5, lane = tid & 31;   // warp covers 4 cols, lane = k-slice
    const float* wc0 = &wC[((warp*4+0)*32 + lane)*WSL];
    const float* wc1 = &wC[((warp*4+1)*32 + lane)*WSL];
    const float* wc2 = &wC[((warp*4+2)*32 + lane)*WSL];
    const float* wc3 = &wC[((warp*4+3)*32 + lane)*WSL];
    const float* ww0 = &wW[((warp*4+0)*32 + lane)*WSL];
    const float* ww1 = &wW[((warp*4+1)*32 + lane)*WSL];
    const float* ww2 = &wW[((warp*4+2)*32 + lane)*WSL];
    const float* ww3 = &wW[((warp*4+3)*32 + lane)*WSL];
    const float* hs0 = &hb[(lane)*WSL];
    const float* hs1 = &hb[(32+lane)*WSL];
    const float* es0 = &eb[(lane)*WSL];
    const float* es1 = &eb[(32+lane)*WSL];

    const int cloc = warp*4 + (lane & 3);   // this lane's col (owners: lane<4)
    const int col  = mbase + cloc;
    const int hv0i = ((col >> 4))*WSL + (col & 15);       // row0 slice of h
    const int hv1i = ((32 + (col >> 4)))*WSL + (col & 15);

    for (int t = 0; t < T_STEPS; ++t) {
        // per-step operand prefetch (owners only), retires under the GEMM
        float pb00=0.f, pb01=0.f, pb10=0.f, pb11=0.f;
        if (lane < 4) {
            size_t r = ((size_t)t*BATCH + b0)*HID + col;
            pb00 = __ldcg(&g_be0[r]);
            pb01 = __ldcg(&g_be0[r + HID]);
            pb10 = __ldcg(&g_be1[r]);
            pb11 = __ldcg(&g_be1[r + HID]);
        }
        float psc0 = __ldcg(&g_scale1[t*BATCH + b0]);
        float psc1 = __ldcg(&g_scale1[t*BATCH + b0 + 1]);

        // load h (2 rows, 4KB) into padded smem
        {
            const float* src = (t == 0) ? (g_hzero + b0*HID)
                                        : (g_hall + ((size_t)(t-1)*BATCH + b0)*HID);
            float4 v = __ldcg(((const float4*)src) + tid);
            int row = tid >> 7, k4 = (tid & 127)*4;
            *(float4*)&hb[(row*32 + (k4>>4))*WSL + (k4&15)] = v;
        }
        __syncthreads();

        // ---- phase A: P = h @ C1^T (4 cols x 2 rows per warp, 32-way k-split)
        float a00=0,a01=0,a10=0,a11=0,a20=0,a21=0,a30=0,a31=0;
        #pragma unroll
        for (int i = 0; i < 4; i++) {
            float4 x0 = *(const float4*)&hs0[i*4];
            float4 x1 = *(const float4*)&hs1[i*4];
            float4 u0 = *(const float4*)&wc0[i*4];
            float4 u1 = *(const float4*)&wc1[i*4];
            float4 u2 = *(const float4*)&wc2[i*4];
            float4 u3 = *(const float4*)&wc3[i*4];
            a00 += u0.x*x0.x + u0.y*x0.y + u0.z*x0.z + u0.w*x0.w;
            a01 += u0.x*x1.x + u0.y*x1.y + u0.z*x1.z + u0.w*x1.w;
            a10 += u1.x*x0.x + u1.y*x0.y + u1.z*x0.z + u1.w*x0.w;
            a11 += u1.x*x1.x + u1.y*x1.y + u1.z*x1.z + u1.w*x1.w;
            a20 += u2.x*x0.x + u2.y*x0.y + u2.z*x0.z + u2.w*x0.w;
            a21 += u2.x*x1.x + u2.y*x1.y + u2.z*x1.z + u2.w*x1.w;
            a30 += u3.x*x0.x + u3.y*x0.y + u3.z*x0.z + u3.w*x0.w;
            a31 += u3.x*x1.x + u3.y*x1.y + u3.z*x1.z + u3.w*x1.w;
        }
        #pragma unroll
        for (int off = 16; off; off >>= 1) {
            a00 += __shfl_xor_sync(0xffffffffu, a00, off);
            a01 += __shfl_xor_sync(0xffffffffu, a01, off);
            a10 += __shfl_xor_sync(0xffffffffu, a10, off);
            a11 += __shfl_xor_sync(0xffffffffu, a11, off);
            a20 += __shfl_xor_sync(0xffffffffu, a20, off);
            a21 += __shfl_xor_sync(0xffffffffu, a21, off);
            a30 += __shfl_xor_sync(0xffffffffu, a30, off);
            a31 += __shfl_xor_sync(0xffffffffu, a31, off);
        }
        float e0 = 0.f, e1 = 0.f;
        if (lane < 4) {
            float p0 = a00, p1 = a01;
            if (lane == 1) { p0 = a10; p1 = a11; }
            if (lane == 2) { p0 = a20; p1 = a21; }
            if (lane == 3) { p0 = a30; p1 = a31; }
            e0 = pb00 - tanhf(p0)*psc0;
            e1 = pb01 - tanhf(p1)*psc1;
            g_err[b0*HID + col]     = e0;
            g_err[(b0+1)*HID + col] = e1;
        }
        float s0 = e0*e0, s1 = e1*e1;     // non-owners contribute 0
        #pragma unroll
        for (int off = 16; off; off >>= 1) {
            s0 += __shfl_xor_sync(0xffffffffu, s0, off);
            s1 += __shfl_xor_sync(0xffffffffu, s1, off);
        }
        if (lane == 0) {
            g_normp[b0*128     + cg*8 + warp] = s0;
            g_normp[(b0+1)*128 + cg*8 + warp] = s1;
        }
        gbar(ctr + 2*t);

        // load full error (2 rows) + reduce norm partials
        {
            float4 v = __ldcg(((const float4*)(g_err + b0*HID)) + tid);
            int row = tid >> 7, k4 = (tid & 127)*4;
            *(float4*)&eb[(row*32 + (k4>>4))*WSL + (k4&15)] = v;
        }
        if (warp < 2) {
            float4 v = __ldcg(((const float4*)(g_normp + (b0+warp)*128)) + lane);
            float s = v.x + v.y + v.z + v.w;
            #pragma unroll
            for (int off = 16; off; off >>= 1) s += __shfl_xor_sync(0xffffffffu, s, off);
            if (lane == 0) snorm[warp] = s;
        }
        __syncthreads();

        // ---- phase B: E = err @ W1^T -> h update ----
        float b00=0,b01=0,b10=0,b11=0,b20=0,b21=0,b30=0,b31=0;
        #pragma unroll
        for (int i = 0; i < 4; i++) {
            float4 x0 = *(const float4*)&es0[i*4];
            float4 x1 = *(const float4*)&es1[i*4];
            float4 u0 = *(const float4*)&ww0[i*4];
            float4 u1 = *(const float4*)&ww1[i*4];
            float4 u2 = *(const float4*)&ww2[i*4];
            float4 u3 = *(const float4*)&ww3[i*4];
            b00 += u0.x*x0.x + u0.y*x0.y + u0.z*x0.z + u0.w*x0.w;
            b01 += u0.x*x1.x + u0.y*x1.y + u0.z*x1.z + u0.w*x1.w;
            b10 += u1.x*x0.x + u1.y*x0.y + u1.z*x0.z + u1.w*x0.w;
            b11 += u1.x*x1.x + u1.y*x1.y + u1.z*x1.z + u1.w*x1.w;
            b20 += u2.x*x0.x + u2.y*x0.y + u2.z*x0.z + u2.w*x0.w;
            b21 += u2.x*x1.x + u2.y*x1.y + u2.z*x1.z + u2.w*x1.w;
            b30 += u3.x*x0.x + u3.y*x0.y + u3.z*x0.z + u3.w*x0.w;
            b31 += u3.x*x1.x + u3.y*x1.y + u3.z*x1.z + u3.w*x1.w;
        }
        #pragma unroll
        for (int off = 16; off; off >>= 1) {
            b00 += __shfl_xor_sync(0xffffffffu, b00, off);
            b01 += __shfl_xor_sync(0xffffffffu, b01, off);
            b10 += __shfl_xor_sync(0xffffffffu, b10, off);
            b11 += __shfl_xor_sync(0xffffffffu, b11, off);
            b20 += __shfl_xor_sync(0xffffffffu, b20, off);
            b21 += __shfl_xor_sync(0xffffffffu, b21, off);
            b30 += __shfl_xor_sync(0xffffffffu, b30, off);
            b31 += __shfl_xor_sync(0xffffffffu, b31, off);
        }
        if (lane < 4) {
            float q0 = b00, q1 = b01;
            if (lane == 1) { q0 = b10; q1 = b11; }
            if (lane == 2) { q0 = b20; q1 = b21; }
            if (lane == 3) { q0 = b30; q1 = b31; }
            float rel0 = fminf(sqrtf(snorm[0])/psc0, 4.f);
            float rel1 = fminf(sqrtf(snorm[1])/psc1, 4.f);
            float sur0 = 1.f/(1.f + expf(-(rel0 - tau)/gam));
            float sur1 = 1.f/(1.f + expf(-(rel1 - tau)/gam));
            float hv0 = hb[hv0i];
            float hv1 = hb[hv1i];
            float ih0 = 0.2f*hv0 + 0.6f*pb10 + 0.2f*sur0*q0;
            float ih1 = 0.2f*hv1 + 0.6f*pb11 + 0.2f*sur1*q1;
            float sg  = sga[cloc];
            float gg0 = sur0*sg, gg1 = sur1*sg;
            size_t orow = ((size_t)t*BATCH + b0)*HID + col;
            g_hall[orow]       = hv0*(1.f - gg0) + tanhf(ih0)*gg0;
            g_hall[orow + HID] = hv1*(1.f - gg1) + tanhf(ih1)*gg1;
        }
        gbar(ctr + 2*t + 1);
    }
}

// ---------------- launch ----------------------------------------------------
extern "C" void kernel_launch(void* const* d_in, const int* in_sizes, int n_in,
                              void* d_out, int out_size)
{
    const float* feats  = (const float*)d_in[0];
    const float* B0     = (const float*)d_in[2];
    const float* C1     = (const float*)d_in[7];
    const float* B1     = (const float*)d_in[8];
    const float* W1     = (const float*)d_in[9];
    const float* a1     = (const float*)d_in[10];
    const float* tau1   = (const float*)d_in[11];
    const float* gam1   = (const float*)d_in[12];
    const float* head_w = (const float*)d_in[13];
    const float* head_b = (const float*)d_in[14];
    float* out = (float*)d_out;

    float *p_xn1, *p_be1, *p_hall;
    cudaGetSymbolAddress((void**)&p_xn1,  g_xn1);
    cudaGetSymbolAddress((void**)&p_be1,  g_be1);
    cudaGetSymbolAddress((void**)&p_hall, g_hall);

    const int SCAN_SMEM = (2*GCOLS*32*WSL + 2*64*WSL + GCOLS + 2 + 30)*4;
    cudaFuncSetAttribute(scan_kernel, cudaFuncAttributeMaxDynamicSharedMemorySize, SCAN_SMEM);

    // launch #0: fused zero + xnorm0 + be0 GEMM
    fused_be0_kernel<<<NROWS/64, 256>>>(feats, B0);
    // launch #1: normalize + clip be0 rows
    xnorm1_kernel<<<(NROWS*32)/256, 256>>>();
    // launch #2: be1 = xn1 @ B1^T  (128x64 tiles)
    dim3 g1(HID/64, NROWS/128);
    sgemm128<<<g1, 256>>>(p_xn1, HID, B1, HID, p_be1, HID, HID, 0, nullptr, 0);
    // launch #3: the scan (ncu capture target) — byte-identical R7 winner
    scan_kernel<<<SCAN_CTAS, 256, SCAN_SMEM>>>(C1, W1, a1, tau1, gam1);
    // head: out = hall @ hw[:, :512]^T + be1 @ hw[:, 512:]^T + bias
    dim3 gh(NCLS/64, NROWS/128);
    sgemm128<<<gh, 256>>>(p_hall, HID, head_w,       2*HID, out, NCLS, HID, 0, nullptr, 1);
    sgemm128<<<gh, 256>>>(p_be1,  HID, head_w + HID, 2*HID, out, NCLS, HID, 1, head_b, 1);
}